// round 13
// baseline (speedup 1.0000x reference)
#include <cuda_runtime.h>
#include <cuda_fp16.h>
#include <cstdint>

// Problem constants
#define BSZ 16384
#define HD  512
#define NC  62
#define UU  8
#define SLAB  ((size_t)BSZ * HD)   // per-unit plane elems (8M)

// ---------------- scratch (device globals; no allocation allowed) -------------
__device__ __align__(16) __half g_xh[(size_t)BSZ * HD];            // x fp16
__device__ __align__(16) __half g_h0[(size_t)UU * BSZ * HD];       // h0 fp16
__device__ __align__(16) __half g_a1[(size_t)UU * BSZ * HD];       // a1 fp16
__device__ __align__(16) __half g_h1[(size_t)UU * BSZ * HD];       // h1 fp16
__device__ __align__(16) __half g_wh[(size_t)2 * 8 * 8 * 512 * 64];  // [(l*8+u)][k8][n512][k64]
__device__ __align__(16) __half g_w2h[(size_t)8 * 8 * 64 * 64];      // [(f*8+k8)][n64][k64]
__device__ float g_c1n[64];
__device__ float g_gbias[64];

// ---------------- helpers -----------------------------------------------------
__device__ __forceinline__ uint32_t smem_to_u32(const void* p) {
    uint32_t a;
    asm("{ .reg .u64 t; cvta.to.shared.u64 t, %1; cvt.u32.u64 %0, t; }" : "=r"(a) : "l"(p));
    return a;
}
__device__ __forceinline__ void ldsm4(uint32_t* r, uint32_t addr) {
    asm volatile("ldmatrix.sync.aligned.m8n8.x4.shared.b16 {%0,%1,%2,%3}, [%4];"
        : "=r"(r[0]), "=r"(r[1]), "=r"(r[2]), "=r"(r[3]) : "r"(addr));
}
__device__ __forceinline__ void mma16816(float* c, const uint32_t* a,
                                         uint32_t b0, uint32_t b1) {
    asm volatile(
        "mma.sync.aligned.m16n8k16.row.col.f32.f16.f16.f32 "
        "{%0,%1,%2,%3}, {%4,%5,%6,%7}, {%8,%9}, {%0,%1,%2,%3};"
        : "+f"(c[0]), "+f"(c[1]), "+f"(c[2]), "+f"(c[3])
        : "r"(a[0]), "r"(a[1]), "r"(a[2]), "r"(a[3]), "r"(b0), "r"(b1));
}
__device__ __forceinline__ void cpa16(uint32_t d, const void* s) {
    asm volatile("cp.async.cg.shared.global [%0], [%1], 16;" :: "r"(d), "l"(s));
}
#define CP_COMMIT() asm volatile("cp.async.commit_group;" ::: "memory")
#define CP_WAIT1()  asm volatile("cp.async.wait_group 1;" ::: "memory")
#define CP_WAIT0()  asm volatile("cp.async.wait_group 0;" ::: "memory")

__device__ __forceinline__ uint32_t pkh(float a, float b) {
    __half ha = __float2half(a), hb = __float2half(b);
    return (uint32_t)__half_as_ushort(ha) | ((uint32_t)__half_as_ushort(hb) << 16);
}

// ============ fused prep: policies + all weight/input conversions =============
__global__ void prep_all(const float* __restrict__ x,
                         const float* __restrict__ p1,
                         const float* __restrict__ p2,
                         const float* __restrict__ pf,
                         const float* __restrict__ W0,
                         const float* __restrict__ W1,
                         const float* __restrict__ W2,
                         const float* __restrict__ b2) {
    const int b = blockIdx.x;
    const int t = threadIdx.x;
    if (b == 0) {
        __shared__ float gs[8];
        if (t == 0) {
            float d = 0.f;
            for (int j = 0; j < 8; j++) d += pf[j];
            float inv = d > 0.f ? 1.f / d : 1.f;
            float acc = 1.f;
            for (int j = 7; j >= 0; --j) { acc *= inv; gs[j] = pf[j] * acc; }
        }
        __syncthreads();
        if (t < 8) {
            float r1 = 0.f;
            for (int f = 0; f < 8; f++) r1 += p1[t * 8 + f];
            float i1 = r1 > 0.f ? 1.f / r1 : 1.f;
            for (int f = 0; f < 8; f++)
                g_c1n[t * 8 + f] = p1[t * 8 + f] * i1;
        }
        if (t < 62) {
            float s = 0.f;
            for (int j = 0; j < 8; j++) s += gs[j] * b2[j * NC + t];
            g_gbias[t] = s;
        } else if (t < 64) {
            g_gbias[t] = 0.f;
        }
    } else if (b < 257) {
        int idx = (b - 1) * 256 + t;
        int n  = idx & 511;
        int r  = idx >> 9;          // (l*8+u)*8 + k8, < 128
        int k8 = r & 7;
        int ug = r >> 3;
        const float* W = (ug >= 8 ? W1 : W0) + ((size_t)(ug & 7) << 18);
        unsigned short hv[64];
        #pragma unroll 8
        for (int i = 0; i < 64; i++)
            hv[i] = __half_as_ushort(__float2half(W[(size_t)(k8 * 64 + i) * 512 + n]));
        __half* dst = g_wh + ((size_t)r * 512 + n) * 64;
        #pragma unroll
        for (int i = 0; i < 8; i++)
            *(uint4*)(dst + i * 8) = *(uint4*)(hv + i * 8);
    } else if (b < 1281) {
        __shared__ float c2s[64];
        if (t < 64) {
            int j = t >> 3;
            float d = 0.f;
            #pragma unroll
            for (int q = 0; q < 8; q++) d += pf[q];
            float inv = d > 0.f ? 1.f / d : 1.f;
            float gsj = pf[j];
            #pragma unroll
            for (int q = 0; q < 8; q++) if (q >= j) gsj *= inv;   // inv^(8-j)
            float r2 = 0.f;
            #pragma unroll
            for (int q = 0; q < 8; q++) r2 += p2[j * 8 + q];
            float i2 = r2 > 0.f ? 1.f / r2 : 1.f;
            c2s[t] = gsj * p2[t] * i2;
        }
        __syncthreads();
        int idx = (b - 257) * 256 + t;   // 262144 total
        int f = idx >> 15;
        int k512 = (idx >> 6) & 511;
        int n = idx & 63;
        float s = 0.f;
        if (n < NC) {
            #pragma unroll
            for (int j = 0; j < 8; j++)
                s = fmaf(c2s[j * 8 + f], W2[((size_t)(j * 512) + k512) * NC + n], s);
        }
        int k8 = k512 >> 6, kk = k512 & 63;
        g_w2h[((size_t)(f * 8 + k8) * 64 + n) * 64 + kk] = __float2half(s);
    } else {
        size_t off = ((size_t)(b - 1281) * 256 + t) << 2;
        float4 v = *(const float4*)(x + off);
        *(uint2*)(g_xh + off) = make_uint2(pkh(v.x, v.y), pkh(v.z, v.w));
    }
}

// ============= fp16 HMMA GEMM: C[u] = relu(A[u] @ W[u] + b[u]) ================
// M=16384, N=512, K=512. BM=128, BN=256, BK=64. 8 warps (2m x 4n), warp 64x64.
// 1 CTA/SM (128 acc regs). 3-stage cp.async ring, one sync per iter.
#define ROWB   144
#define APLANE (128 * ROWB)          // 18432
#define BPLANE (256 * ROWB)          // 36864
#define STG    (APLANE + BPLANE)     // 55296
#define GEMM_SMEM (3 * STG)          // 165888

__global__ __launch_bounds__(256, 1)
void gemm_fp16(int srcSel, int layer, const float* __restrict__ bias, int outSel) {
    extern __shared__ __align__(16) char dsm[];
    __shared__ float sBias[512];
    const uint32_t sdyn = smem_to_u32(dsm);

    const int tid = threadIdx.x;
    const int wid = tid >> 5, lane = tid & 31;
    const int g = lane >> 2, t4 = lane & 3;
    const int wm = (wid & 1) * 64;        // 2 warp rows over BM=128
    const int wn = (wid >> 1) * 64;       // 4 warp cols over BN=256
    const int u  = blockIdx.z;
    const int bm = blockIdx.x * 128;
    const int bn0 = blockIdx.y * 256;

    // ldmatrix lane decodes (validated R5-R12)
    const int la  = (lane & 7) + ((lane >> 3) & 1) * 8;
    const int lk  = (lane >> 4) * 16;
    const int lbn = (lane & 7) + ((lane >> 4) & 1) * 8;
    const int lbk = ((lane >> 3) & 1) * 16;

    const __half* AU = (srcSel == 0) ? g_xh : (g_a1 + (size_t)u * SLAB);
    AU += (size_t)bm * HD;
    const __half* Wb = g_wh + (size_t)(layer * 8 + u) * 262144;
    __half* OH = (outSel ? g_h1 : g_h0) + (size_t)u * SLAB + (size_t)bm * HD + bn0;

    ((float2*)sBias)[tid] = ((const float2*)(bias + u * HD))[tid];

    float acc[4][8][4];
    #pragma unroll
    for (int i = 0; i < 4; i++)
        #pragma unroll
        for (int j = 0; j < 8; j++)
            #pragma unroll
            for (int q = 0; q < 4; q++) acc[i][j][q] = 0.f;

    auto issue = [&](int kt, int bufI) {
        uint32_t sbuf = sdyn + bufI * STG;
        const __half* Ap = AU + kt * 64;
        const __half* Bp = Wb + (size_t)kt * 32768 + (size_t)bn0 * 64;
        #pragma unroll
        for (int i = 0; i < 4; i++) {       // A: 1024 chunks
            int c = i * 256 + tid, row = c >> 3, q = c & 7;
            cpa16(sbuf + row * ROWB + q * 16, Ap + (size_t)row * HD + q * 8);
        }
        #pragma unroll
        for (int i = 0; i < 8; i++) {       // B: 2048 chunks
            int c = i * 256 + tid, row = c >> 3, q = c & 7;
            cpa16(sbuf + APLANE + row * ROWB + q * 16, Bp + (size_t)row * 64 + q * 8);
        }
        CP_COMMIT();
    };

    issue(0, 0);
    issue(1, 1);

    #pragma unroll 1
    for (int kt = 0; kt < 8; ++kt) {
        if (kt < 7) CP_WAIT1(); else CP_WAIT0();
        __syncthreads();                   // tile kt visible; buf (kt+2)%3 consumed
        if (kt < 6) issue(kt + 2, (kt + 2) % 3);

        const uint32_t aB = sdyn + (kt % 3) * STG;
        const uint32_t bB = aB + APLANE;
        uint32_t af[2][4][4], bf[2][4][4];
        #pragma unroll
        for (int i = 0; i < 4; i++)
            ldsm4(af[0][i], aB + (wm + 16 * i + la) * ROWB + lk);
        #pragma unroll
        for (int jp = 0; jp < 4; jp++)
            ldsm4(bf[0][jp], bB + (wn + 16 * jp + lbn) * ROWB + lbk);

        #pragma unroll
        for (int k16 = 0; k16 < 4; k16++) {
            const int cur = k16 & 1, nxt = cur ^ 1;
            if (k16 < 3) {
                const int kb = (k16 + 1) * 32;
                #pragma unroll
                for (int i = 0; i < 4; i++)
                    ldsm4(af[nxt][i], aB + (wm + 16 * i + la) * ROWB + kb + lk);
                #pragma unroll
                for (int jp = 0; jp < 4; jp++)
                    ldsm4(bf[nxt][jp], bB + (wn + 16 * jp + lbn) * ROWB + kb + lbk);
            }
            #pragma unroll
            for (int jp = 0; jp < 4; jp++) {
                #pragma unroll
                for (int jj = 0; jj < 2; jj++) {
                    const int j = 2 * jp + jj;
                    #pragma unroll
                    for (int i = 0; i < 4; i++)
                        mma16816(acc[i][j], af[cur][i],
                                 bf[cur][jp][2 * jj], bf[cur][jp][2 * jj + 1]);
                }
            }
        }
    }

    // ---- epilogue: bias + relu -> fp16 ----
    #pragma unroll
    for (int i = 0; i < 4; i++) {
        #pragma unroll
        for (int j = 0; j < 8; j++) {
            int cb = wn + 8 * j + t4 * 2;
            float b0 = sBias[bn0 + cb], b1 = sBias[bn0 + cb + 1];
            float v0 = acc[i][j][0] + b0, v1 = acc[i][j][1] + b1;
            float v2 = acc[i][j][2] + b0, v3 = acc[i][j][3] + b1;
            v0 = v0 > 0.f ? v0 : 0.f; v1 = v1 > 0.f ? v1 : 0.f;
            v2 = v2 > 0.f ? v2 : 0.f; v3 = v3 > 0.f ? v3 : 0.f;
            int m0 = wm + 16 * i + g;
            *(uint32_t*)(OH + (size_t)m0 * HD + cb)       = pkh(v0, v1);
            *(uint32_t*)(OH + (size_t)(m0 + 8) * HD + cb) = pkh(v2, v3);
        }
    }
}

// ---------------- aggregation: a1[t] = sum_f c1n[t,f]*h0[f] (fp16, 8/thread) ---
__global__ void agg1_kernel() {
    __shared__ float c1s[64];
    int t = threadIdx.x;
    if (t < 64) c1s[t] = g_c1n[t];
    __syncthreads();
    size_t off = ((size_t)blockIdx.x * 256 + t) << 3;   // 8 halves per thread
    float2 h[8][4];
    #pragma unroll
    for (int f = 0; f < 8; f++) {
        uint4 p = *(const uint4*)(g_h0 + (size_t)f * SLAB + off);
        h[f][0] = __half22float2(*(const __half2*)&p.x);
        h[f][1] = __half22float2(*(const __half2*)&p.y);
        h[f][2] = __half22float2(*(const __half2*)&p.z);
        h[f][3] = __half22float2(*(const __half2*)&p.w);
    }
    #pragma unroll
    for (int u = 0; u < 8; u++) {
        float s[8];
        #pragma unroll
        for (int q = 0; q < 8; q++) s[q] = 0.f;
        #pragma unroll
        for (int f = 0; f < 8; f++) {
            float c = c1s[u * 8 + f];
            #pragma unroll
            for (int q = 0; q < 4; q++) {
                s[2 * q]     = fmaf(c, h[f][q].x, s[2 * q]);
                s[2 * q + 1] = fmaf(c, h[f][q].y, s[2 * q + 1]);
            }
        }
        *(uint4*)(g_a1 + (size_t)u * SLAB + off) =
            make_uint4(pkh(s[0], s[1]), pkh(s[2], s[3]), pkh(s[4], s[5]), pkh(s[6], s[7]));
    }
}

// ============ fp16 output GEMM: out = sum_f h1[f] @ W2eff[f] + gbias ==========
// M=16384 (BM=64), N=64, K=4096 (8 f x 8 k8 x 64). 8 warps 4x2, warp tile 16x32.
#define OPLANE (64 * ROWB)          // 9216
#define OSTG   (2 * OPLANE)         // 18432
#define OUT_SMEM (2 * OSTG)         // 36864

__global__ __launch_bounds__(256, 2)
void gemm_out_tc(float* __restrict__ Out) {
    extern __shared__ __align__(16) char dsm[];
    const uint32_t sdyn = smem_to_u32(dsm);
    const int tid = threadIdx.x;
    const int wid = tid >> 5, lane = tid & 31;
    const int g = lane >> 2, t4 = lane & 3;
    const int wm = (wid & 3) * 16;
    const int wn = (wid >> 2) * 32;
    const int bm = blockIdx.x * 64;

    const int la  = (lane & 7) + ((lane >> 3) & 1) * 8;
    const int lk  = (lane >> 4) * 16;
    const int lbn = (lane & 7) + ((lane >> 4) & 1) * 8;
    const int lbk = ((lane >> 3) & 1) * 16;

    float acc[4][4];
    #pragma unroll
    for (int j = 0; j < 4; j++)
        #pragma unroll
        for (int q = 0; q < 4; q++) acc[j][q] = 0.f;

    const int r0 = tid >> 3, q0 = tid & 7;   // 32 rows per i-step

    auto issue = [&](int it, int bufI) {
        uint32_t sbuf = sdyn + bufI * OSTG;
        int f = it >> 3, k8 = it & 7;
        const __half* Ap = g_h1 + (size_t)f * SLAB + (size_t)bm * HD + k8 * 64;
        const __half* Bp = g_w2h + (size_t)(f * 8 + k8) * 4096;
        #pragma unroll
        for (int i = 0; i < 2; i++) {
            int row = r0 + i * 32;
            cpa16(sbuf + row * ROWB + q0 * 16, Ap + (size_t)row * HD + q0 * 8);
            cpa16(sbuf + OPLANE + row * ROWB + q0 * 16, Bp + (size_t)row * 64 + q0 * 8);
        }
        CP_COMMIT();
    };

    issue(0, 0);

    #pragma unroll 1
    for (int it = 0; it < 64; ++it) {
        const int s = it & 1;
        CP_WAIT0();
        __syncthreads();
        if (it < 63) issue(it + 1, 1 - s);

        const uint32_t aB = sdyn + s * OSTG;
        const uint32_t bB = aB + OPLANE;
        uint32_t af[2][4], bf[2][2][4];
        ldsm4(af[0], aB + (wm + la) * ROWB + lk);
        #pragma unroll
        for (int jp = 0; jp < 2; jp++)
            ldsm4(bf[0][jp], bB + (wn + 16 * jp + lbn) * ROWB + lbk);

        #pragma unroll
        for (int k16 = 0; k16 < 4; k16++) {
            const int cur = k16 & 1, nxt = cur ^ 1;
            if (k16 < 3) {
                const int kb = (k16 + 1) * 32;
                ldsm4(af[nxt], aB + (wm + la) * ROWB + kb + lk);
                #pragma unroll
                for (int jp = 0; jp < 2; jp++)
                    ldsm4(bf[nxt][jp], bB + (wn + 16 * jp + lbn) * ROWB + kb + lbk);
            }
            #pragma unroll
            for (int jp = 0; jp < 2; jp++) {
                mma16816(acc[2 * jp],     af[cur], bf[cur][jp][0], bf[cur][jp][1]);
                mma16816(acc[2 * jp + 1], af[cur], bf[cur][jp][2], bf[cur][jp][3]);
            }
        }
    }

    // epilogue: + gbias, store (cols < NC)
    #pragma unroll
    for (int j = 0; j < 4; j++) {
        int c = wn + 8 * j + 2 * t4;
        float b0 = g_gbias[c], b1 = g_gbias[c + 1];
        int m0 = bm + wm + g;
        float v0 = acc[j][0] + b0, v1 = acc[j][1] + b1;
        float v2 = acc[j][2] + b0, v3 = acc[j][3] + b1;
        if (c < NC)     Out[(size_t)m0 * NC + c]           = v0;
        if (c + 1 < NC) Out[(size_t)m0 * NC + c + 1]       = v1;
        if (c < NC)     Out[(size_t)(m0 + 8) * NC + c]     = v2;
        if (c + 1 < NC) Out[(size_t)(m0 + 8) * NC + c + 1] = v3;
    }
}

// ---------------- launch ------------------------------------------------------
extern "C" void kernel_launch(void* const* d_in, const int* in_sizes, int n_in,
                              void* d_out, int out_size) {
    const float* x  = (const float*)d_in[0];
    const float* p1 = (const float*)d_in[1];
    const float* p2 = (const float*)d_in[2];
    const float* pf = (const float*)d_in[3];
    const float* W0 = (const float*)d_in[4];
    const float* b0 = (const float*)d_in[5];
    const float* W1 = (const float*)d_in[6];
    const float* b1 = (const float*)d_in[7];
    const float* W2 = (const float*)d_in[8];
    const float* b2 = (const float*)d_in[9];
    float* out = (float*)d_out;

    cudaFuncSetAttribute(gemm_fp16, cudaFuncAttributeMaxDynamicSharedMemorySize, GEMM_SMEM);
    cudaFuncSetAttribute(gemm_out_tc, cudaFuncAttributeMaxDynamicSharedMemorySize, OUT_SMEM);

    // all policy folds + fp16 conversions in one launch
    prep_all<<<9473, 256>>>(x, p1, p2, pf, W0, W1, W2, b2);

    // stage A: h0[u] = relu(x @ W0[u] + b0[u]) -> g_h0 fp16
    gemm_fp16<<<dim3(128, 2, 8), 256, GEMM_SMEM>>>(0, 0, b0, 0);

    // aggregation: a1 = c1n-mix(h0) -> g_a1 fp16
    agg1_kernel<<<4096, 256>>>();

    // stage C: h1[u] = relu(a1[u] @ W1[u] + b1[u]) -> g_h1 fp16
    gemm_fp16<<<dim3(128, 2, 8), 256, GEMM_SMEM>>>(1, 1, b1, 1);

    // output: out = sum_f h1[f] @ W2eff[f] + gbias
    gemm_out_tc<<<256, 256, OUT_SMEM>>>(out);
}

// round 15
// speedup vs baseline: 1.6358x; 1.6358x over previous
#include <cuda_runtime.h>
#include <cuda_fp16.h>
#include <cstdint>

// Problem constants
#define BSZ 16384
#define HD  512
#define NC  62
#define UU  8
#define SLAB  ((size_t)BSZ * HD)   // per-unit plane elems (8M)

// ---------------- scratch (device globals; no allocation allowed) -------------
__device__ __align__(16) __half g_xh[(size_t)BSZ * HD];            // x fp16
__device__ __align__(16) __half g_h0[(size_t)UU * BSZ * HD];       // h0 fp16
__device__ __align__(16) __half g_a1[(size_t)UU * BSZ * HD];       // a1 fp16
__device__ __align__(16) __half g_h1[(size_t)UU * BSZ * HD];       // h1 fp16
__device__ __align__(16) __half g_wh[(size_t)2 * 8 * 8 * 512 * 64];  // [(l*8+u)][k8][n512][k64]
__device__ __align__(16) __half g_w2h[(size_t)8 * 8 * 64 * 64];      // [(f*8+k8)][n64][k64]
__device__ float g_c1n[64];
__device__ float g_gbias[64];

// ---------------- helpers -----------------------------------------------------
__device__ __forceinline__ uint32_t smem_to_u32(const void* p) {
    uint32_t a;
    asm("{ .reg .u64 t; cvta.to.shared.u64 t, %1; cvt.u32.u64 %0, t; }" : "=r"(a) : "l"(p));
    return a;
}
__device__ __forceinline__ void ldsm4(uint32_t* r, uint32_t addr) {
    asm volatile("ldmatrix.sync.aligned.m8n8.x4.shared.b16 {%0,%1,%2,%3}, [%4];"
        : "=r"(r[0]), "=r"(r[1]), "=r"(r[2]), "=r"(r[3]) : "r"(addr));
}
__device__ __forceinline__ void mma16816(float* c, const uint32_t* a,
                                         uint32_t b0, uint32_t b1) {
    asm volatile(
        "mma.sync.aligned.m16n8k16.row.col.f32.f16.f16.f32 "
        "{%0,%1,%2,%3}, {%4,%5,%6,%7}, {%8,%9}, {%0,%1,%2,%3};"
        : "+f"(c[0]), "+f"(c[1]), "+f"(c[2]), "+f"(c[3])
        : "r"(a[0]), "r"(a[1]), "r"(a[2]), "r"(a[3]), "r"(b0), "r"(b1));
}
__device__ __forceinline__ void cpa16(uint32_t d, const void* s) {
    asm volatile("cp.async.cg.shared.global [%0], [%1], 16;" :: "r"(d), "l"(s));
}
#define CP_COMMIT() asm volatile("cp.async.commit_group;" ::: "memory")
#define CP_WAIT0()  asm volatile("cp.async.wait_group 0;" ::: "memory")

__device__ __forceinline__ uint32_t pkh(float a, float b) {
    __half ha = __float2half(a), hb = __float2half(b);
    return (uint32_t)__half_as_ushort(ha) | ((uint32_t)__half_as_ushort(hb) << 16);
}

// ============ fused prep: policies + all weight/input conversions =============
__global__ void prep_all(const float* __restrict__ x,
                         const float* __restrict__ p1,
                         const float* __restrict__ p2,
                         const float* __restrict__ pf,
                         const float* __restrict__ W0,
                         const float* __restrict__ W1,
                         const float* __restrict__ W2,
                         const float* __restrict__ b2) {
    const int b = blockIdx.x;
    const int t = threadIdx.x;
    if (b == 0) {
        __shared__ float gs[8];
        if (t == 0) {
            float d = 0.f;
            for (int j = 0; j < 8; j++) d += pf[j];
            float inv = d > 0.f ? 1.f / d : 1.f;
            float acc = 1.f;
            for (int j = 7; j >= 0; --j) { acc *= inv; gs[j] = pf[j] * acc; }
        }
        __syncthreads();
        if (t < 8) {
            float r1 = 0.f;
            for (int f = 0; f < 8; f++) r1 += p1[t * 8 + f];
            float i1 = r1 > 0.f ? 1.f / r1 : 1.f;
            for (int f = 0; f < 8; f++)
                g_c1n[t * 8 + f] = p1[t * 8 + f] * i1;
        }
        if (t < 62) {
            float s = 0.f;
            for (int j = 0; j < 8; j++) s += gs[j] * b2[j * NC + t];
            g_gbias[t] = s;
        } else if (t < 64) {
            g_gbias[t] = 0.f;
        }
    } else if (b < 257) {
        int idx = (b - 1) * 256 + t;
        int n  = idx & 511;
        int r  = idx >> 9;          // (l*8+u)*8 + k8, < 128
        int k8 = r & 7;
        int ug = r >> 3;
        const float* W = (ug >= 8 ? W1 : W0) + ((size_t)(ug & 7) << 18);
        unsigned short hv[64];
        #pragma unroll 8
        for (int i = 0; i < 64; i++)
            hv[i] = __half_as_ushort(__float2half(W[(size_t)(k8 * 64 + i) * 512 + n]));
        __half* dst = g_wh + ((size_t)r * 512 + n) * 64;
        #pragma unroll
        for (int i = 0; i < 8; i++)
            *(uint4*)(dst + i * 8) = *(uint4*)(hv + i * 8);
    } else if (b < 1281) {
        __shared__ float c2s[64];
        if (t < 64) {
            int j = t >> 3;
            float d = 0.f;
            #pragma unroll
            for (int q = 0; q < 8; q++) d += pf[q];
            float inv = d > 0.f ? 1.f / d : 1.f;
            float gsj = pf[j];
            #pragma unroll
            for (int q = 0; q < 8; q++) if (q >= j) gsj *= inv;   // inv^(8-j)
            float r2 = 0.f;
            #pragma unroll
            for (int q = 0; q < 8; q++) r2 += p2[j * 8 + q];
            float i2 = r2 > 0.f ? 1.f / r2 : 1.f;
            c2s[t] = gsj * p2[t] * i2;
        }
        __syncthreads();
        int idx = (b - 257) * 256 + t;   // 262144 total
        int f = idx >> 15;
        int k512 = (idx >> 6) & 511;
        int n = idx & 63;
        float s = 0.f;
        if (n < NC) {
            #pragma unroll
            for (int j = 0; j < 8; j++)
                s = fmaf(c2s[j * 8 + f], W2[((size_t)(j * 512) + k512) * NC + n], s);
        }
        int k8 = k512 >> 6, kk = k512 & 63;
        g_w2h[((size_t)(f * 8 + k8) * 64 + n) * 64 + kk] = __float2half(s);
    } else {
        size_t off = ((size_t)(b - 1281) * 256 + t) << 2;
        float4 v = *(const float4*)(x + off);
        *(uint2*)(g_xh + off) = make_uint2(pkh(v.x, v.y), pkh(v.z, v.w));
    }
}

// ============= fp16 HMMA GEMM: C[u] = relu(A[u] @ W[u] + b[u]) ================
// M=16384, N=512, K=512. BM=128, BN=128, BK=64. 8 warps 4x2, warp tile 32x64.
// SMEM rows 144 B. 2-stage race-free ring; frag double-buffering; preload-first.
#define ROWB  144
#define PLANE (128 * ROWB)          // 18432
#define STG   (2 * PLANE)           // 36864
#define GEMM_SMEM (2 * STG)         // 73728

__global__ __launch_bounds__(256, 2)
void gemm_fp16(int srcSel, int layer, const float* __restrict__ bias, int outSel) {
    extern __shared__ __align__(16) char dsm[];
    __shared__ float sBias[512];
    const uint32_t sdyn = smem_to_u32(dsm);

    const int tid = threadIdx.x;
    const int wid = tid >> 5, lane = tid & 31;
    const int g = lane >> 2, t4 = lane & 3;
    const int wm = (wid >> 1) * 32;
    const int wn = (wid & 1) * 64;
    const int u  = blockIdx.z;
    const int bm = blockIdx.x * 128;
    const int bn = blockIdx.y * 128;

    // ldmatrix lane decodes (validated R5-R12)
    const int la  = (lane & 7) + ((lane >> 3) & 1) * 8;
    const int lk  = (lane >> 4) * 16;
    const int lbn = (lane & 7) + ((lane >> 4) & 1) * 8;
    const int lbk = ((lane >> 3) & 1) * 16;

    const __half* AU = (srcSel == 0) ? g_xh : (g_a1 + (size_t)u * SLAB);
    AU += (size_t)bm * HD;
    const __half* Wb = g_wh + (size_t)(layer * 8 + u) * 262144;
    __half* OH = (outSel ? g_h1 : g_h0) + (size_t)u * SLAB + (size_t)bm * HD + bn;

    ((float2*)sBias)[tid] = ((const float2*)(bias + u * HD))[tid];

    float acc[2][8][4];
    #pragma unroll
    for (int i = 0; i < 2; i++)
        #pragma unroll
        for (int j = 0; j < 8; j++)
            #pragma unroll
            for (int q = 0; q < 4; q++) acc[i][j][q] = 0.f;

    const int r0 = tid >> 3, q0 = tid & 7;   // staging lane map

    auto issue = [&](int kt, int bufI) {
        uint32_t sbuf = sdyn + bufI * STG;
        const __half* Ap = AU + kt * 64;
        const __half* Bp = Wb + (size_t)kt * 32768 + (size_t)bn * 64;
        #pragma unroll
        for (int i = 0; i < 4; i++) {
            int row = r0 + i * 32;
            cpa16(sbuf + row * ROWB + q0 * 16,         Ap + (size_t)row * HD + q0 * 8);
            cpa16(sbuf + PLANE + row * ROWB + q0 * 16, Bp + (size_t)row * 64 + q0 * 8);
        }
        CP_COMMIT();
    };

    issue(0, 0);

    #pragma unroll 1
    for (int kt = 0; kt < 8; ++kt) {
        const int s = kt & 1;
        CP_WAIT0();                 // tile kt landed (overlapped with compute kt-1)
        __syncthreads();            // visible to all; buf 1-s fully consumed

        const uint32_t aB = sdyn + s * STG;
        const uint32_t bB = aB + PLANE;
        uint32_t af[2][2][4], bf[2][4][4];
        // critical path first: preload k16-group 0 fragments
        ldsm4(af[0][0], aB + (wm + la) * ROWB + lk);
        ldsm4(af[0][1], aB + (wm + 16 + la) * ROWB + lk);
        #pragma unroll
        for (int jp = 0; jp < 4; jp++)
            ldsm4(bf[0][jp], bB + (wn + 16 * jp + lbn) * ROWB + lbk);

        // next tile's loads are off the critical path — issue after preload
        if (kt < 7) issue(kt + 1, 1 - s);

        #pragma unroll
        for (int k16 = 0; k16 < 4; k16++) {
            const int cur = k16 & 1, nxt = cur ^ 1;
            if (k16 < 3) {
                const int kb = (k16 + 1) * 32;
                ldsm4(af[nxt][0], aB + (wm + la) * ROWB + kb + lk);
                ldsm4(af[nxt][1], aB + (wm + 16 + la) * ROWB + kb + lk);
                #pragma unroll
                for (int jp = 0; jp < 4; jp++)
                    ldsm4(bf[nxt][jp], bB + (wn + 16 * jp + lbn) * ROWB + kb + lbk);
            }
            #pragma unroll
            for (int jp = 0; jp < 4; jp++) {
                #pragma unroll
                for (int jj = 0; jj < 2; jj++) {
                    const int j = 2 * jp + jj;
                    mma16816(acc[0][j], af[cur][0], bf[cur][jp][2 * jj], bf[cur][jp][2 * jj + 1]);
                    mma16816(acc[1][j], af[cur][1], bf[cur][jp][2 * jj], bf[cur][jp][2 * jj + 1]);
                }
            }
        }
    }

    // ---- epilogue: bias + relu -> fp16 ----
    #pragma unroll
    for (int i = 0; i < 2; i++) {
        #pragma unroll
        for (int j = 0; j < 8; j++) {
            int cb = wn + 8 * j + t4 * 2;
            float b0 = sBias[bn + cb], b1 = sBias[bn + cb + 1];
            float v0 = acc[i][j][0] + b0, v1 = acc[i][j][1] + b1;
            float v2 = acc[i][j][2] + b0, v3 = acc[i][j][3] + b1;
            v0 = v0 > 0.f ? v0 : 0.f; v1 = v1 > 0.f ? v1 : 0.f;
            v2 = v2 > 0.f ? v2 : 0.f; v3 = v3 > 0.f ? v3 : 0.f;
            int m0 = wm + 16 * i + g;
            *(uint32_t*)(OH + (size_t)m0 * HD + cb)       = pkh(v0, v1);
            *(uint32_t*)(OH + (size_t)(m0 + 8) * HD + cb) = pkh(v2, v3);
        }
    }
}

// ---------------- aggregation: a1[t] = sum_f c1n[t,f]*h0[f] (fp16, 8/thread) ---
__global__ void agg1_kernel() {
    __shared__ float c1s[64];
    int t = threadIdx.x;
    if (t < 64) c1s[t] = g_c1n[t];
    __syncthreads();
    size_t off = ((size_t)blockIdx.x * 256 + t) << 3;   // 8 halves per thread
    float2 h[8][4];
    #pragma unroll
    for (int f = 0; f < 8; f++) {
        uint4 p = *(const uint4*)(g_h0 + (size_t)f * SLAB + off);
        h[f][0] = __half22float2(*(const __half2*)&p.x);
        h[f][1] = __half22float2(*(const __half2*)&p.y);
        h[f][2] = __half22float2(*(const __half2*)&p.z);
        h[f][3] = __half22float2(*(const __half2*)&p.w);
    }
    #pragma unroll
    for (int u = 0; u < 8; u++) {
        float s[8];
        #pragma unroll
        for (int q = 0; q < 8; q++) s[q] = 0.f;
        #pragma unroll
        for (int f = 0; f < 8; f++) {
            float c = c1s[u * 8 + f];
            #pragma unroll
            for (int q = 0; q < 4; q++) {
                s[2 * q]     = fmaf(c, h[f][q].x, s[2 * q]);
                s[2 * q + 1] = fmaf(c, h[f][q].y, s[2 * q + 1]);
            }
        }
        *(uint4*)(g_a1 + (size_t)u * SLAB + off) =
            make_uint4(pkh(s[0], s[1]), pkh(s[2], s[3]), pkh(s[4], s[5]), pkh(s[6], s[7]));
    }
}

// ============ fp16 output GEMM: out = sum_f h1[f] @ W2eff[f] + gbias ==========
// M=16384 (BM=64), N=64, K=4096 (8 f x 8 k8 x 64). 8 warps 4x2, warp tile 16x32.
#define OPLANE (64 * ROWB)          // 9216
#define OSTG   (2 * OPLANE)         // 18432
#define OUT_SMEM (2 * OSTG)         // 36864

__global__ __launch_bounds__(256, 2)
void gemm_out_tc(float* __restrict__ Out) {
    extern __shared__ __align__(16) char dsm[];
    const uint32_t sdyn = smem_to_u32(dsm);
    const int tid = threadIdx.x;
    const int wid = tid >> 5, lane = tid & 31;
    const int g = lane >> 2, t4 = lane & 3;
    const int wm = (wid & 3) * 16;
    const int wn = (wid >> 2) * 32;
    const int bm = blockIdx.x * 64;

    const int la  = (lane & 7) + ((lane >> 3) & 1) * 8;
    const int lk  = (lane >> 4) * 16;
    const int lbn = (lane & 7) + ((lane >> 4) & 1) * 8;
    const int lbk = ((lane >> 3) & 1) * 16;

    float acc[4][4];
    #pragma unroll
    for (int j = 0; j < 4; j++)
        #pragma unroll
        for (int q = 0; q < 4; q++) acc[j][q] = 0.f;

    const int r0 = tid >> 3, q0 = tid & 7;   // 32 rows per i-step

    auto issue = [&](int it, int bufI) {
        uint32_t sbuf = sdyn + bufI * OSTG;
        int f = it >> 3, k8 = it & 7;
        const __half* Ap = g_h1 + (size_t)f * SLAB + (size_t)bm * HD + k8 * 64;
        const __half* Bp = g_w2h + (size_t)(f * 8 + k8) * 4096;
        #pragma unroll
        for (int i = 0; i < 2; i++) {
            int row = r0 + i * 32;
            cpa16(sbuf + row * ROWB + q0 * 16, Ap + (size_t)row * HD + q0 * 8);
            cpa16(sbuf + OPLANE + row * ROWB + q0 * 16, Bp + (size_t)row * 64 + q0 * 8);
        }
        CP_COMMIT();
    };

    issue(0, 0);

    #pragma unroll 1
    for (int it = 0; it < 64; ++it) {
        const int s = it & 1;
        CP_WAIT0();
        __syncthreads();

        const uint32_t aB = sdyn + s * OSTG;
        const uint32_t bB = aB + OPLANE;
        uint32_t af[2][4], bf[2][2][4];
        ldsm4(af[0], aB + (wm + la) * ROWB + lk);
        #pragma unroll
        for (int jp = 0; jp < 2; jp++)
            ldsm4(bf[0][jp], bB + (wn + 16 * jp + lbn) * ROWB + lbk);

        if (it < 63) issue(it + 1, 1 - s);

        #pragma unroll
        for (int k16 = 0; k16 < 4; k16++) {
            const int cur = k16 & 1, nxt = cur ^ 1;
            if (k16 < 3) {
                const int kb = (k16 + 1) * 32;
                ldsm4(af[nxt], aB + (wm + la) * ROWB + kb + lk);
                #pragma unroll
                for (int jp = 0; jp < 2; jp++)
                    ldsm4(bf[nxt][jp], bB + (wn + 16 * jp + lbn) * ROWB + kb + lbk);
            }
            #pragma unroll
            for (int jp = 0; jp < 2; jp++) {
                mma16816(acc[2 * jp],     af[cur], bf[cur][jp][0], bf[cur][jp][1]);
                mma16816(acc[2 * jp + 1], af[cur], bf[cur][jp][2], bf[cur][jp][3]);
            }
        }
    }

    // epilogue: + gbias, store (cols < NC)
    #pragma unroll
    for (int j = 0; j < 4; j++) {
        int c = wn + 8 * j + 2 * t4;
        float b0 = g_gbias[c], b1 = g_gbias[c + 1];
        int m0 = bm + wm + g;
        float v0 = acc[j][0] + b0, v1 = acc[j][1] + b1;
        float v2 = acc[j][2] + b0, v3 = acc[j][3] + b1;
        if (c < NC)     Out[(size_t)m0 * NC + c]           = v0;
        if (c + 1 < NC) Out[(size_t)m0 * NC + c + 1]       = v1;
        if (c < NC)     Out[(size_t)(m0 + 8) * NC + c]     = v2;
        if (c + 1 < NC) Out[(size_t)(m0 + 8) * NC + c + 1] = v3;
    }
}

// ---------------- launch ------------------------------------------------------
extern "C" void kernel_launch(void* const* d_in, const int* in_sizes, int n_in,
                              void* d_out, int out_size) {
    const float* x  = (const float*)d_in[0];
    const float* p1 = (const float*)d_in[1];
    const float* p2 = (const float*)d_in[2];
    const float* pf = (const float*)d_in[3];
    const float* W0 = (const float*)d_in[4];
    const float* b0 = (const float*)d_in[5];
    const float* W1 = (const float*)d_in[6];
    const float* b1 = (const float*)d_in[7];
    const float* W2 = (const float*)d_in[8];
    const float* b2 = (const float*)d_in[9];
    float* out = (float*)d_out;

    cudaFuncSetAttribute(gemm_fp16, cudaFuncAttributeMaxDynamicSharedMemorySize, GEMM_SMEM);
    cudaFuncSetAttribute(gemm_out_tc, cudaFuncAttributeMaxDynamicSharedMemorySize, OUT_SMEM);

    // all policy folds + fp16 conversions in one launch
    prep_all<<<9473, 256>>>(x, p1, p2, pf, W0, W1, W2, b2);

    // stage A: h0[u] = relu(x @ W0[u] + b0[u]) -> g_h0 fp16
    gemm_fp16<<<dim3(128, 4, 8), 256, GEMM_SMEM>>>(0, 0, b0, 0);

    // aggregation: a1 = c1n-mix(h0) -> g_a1 fp16
    agg1_kernel<<<4096, 256>>>();

    // stage C: h1[u] = relu(a1[u] @ W1[u] + b1[u]) -> g_h1 fp16
    gemm_fp16<<<dim3(128, 4, 8), 256, GEMM_SMEM>>>(1, 1, b1, 1);

    // output: out = sum_f h1[f] @ W2eff[f] + gbias
    gemm_out_tc<<<256, 256, OUT_SMEM>>>(out);
}

// round 16
// speedup vs baseline: 1.7148x; 1.0483x over previous
#include <cuda_runtime.h>
#include <cuda_fp16.h>
#include <cstdint>

// Problem constants
#define BSZ 16384
#define HD  512
#define NC  62
#define UU  8
#define SLAB  ((size_t)BSZ * HD)   // per-unit plane elems (8M)

// ---------------- scratch (device globals; no allocation allowed) -------------
__device__ __align__(16) __half g_xh[(size_t)BSZ * HD];            // x fp16
__device__ __align__(16) __half g_h0[(size_t)UU * BSZ * HD];       // h0 fp16
__device__ __align__(16) __half g_a1[(size_t)UU * BSZ * HD];       // a1 fp16
__device__ __align__(16) __half g_h1[(size_t)UU * BSZ * HD];       // h1 fp16
__device__ __align__(16) __half g_wh[(size_t)2 * 8 * 8 * 512 * 64];  // [(l*8+u)][k8][n512][k64]
__device__ __align__(16) __half g_w2h[(size_t)8 * 8 * 64 * 64];      // [(f*8+k8)][n64][k64]
__device__ float g_c1n[64];
__device__ float g_gbias[64];

// ---------------- helpers -----------------------------------------------------
__device__ __forceinline__ uint32_t smem_to_u32(const void* p) {
    uint32_t a;
    asm("{ .reg .u64 t; cvta.to.shared.u64 t, %1; cvt.u32.u64 %0, t; }" : "=r"(a) : "l"(p));
    return a;
}
__device__ __forceinline__ void ldsm4(uint32_t* r, uint32_t addr) {
    asm volatile("ldmatrix.sync.aligned.m8n8.x4.shared.b16 {%0,%1,%2,%3}, [%4];"
        : "=r"(r[0]), "=r"(r[1]), "=r"(r[2]), "=r"(r[3]) : "r"(addr));
}
__device__ __forceinline__ void mma16816(float* c, const uint32_t* a,
                                         uint32_t b0, uint32_t b1) {
    asm volatile(
        "mma.sync.aligned.m16n8k16.row.col.f32.f16.f16.f32 "
        "{%0,%1,%2,%3}, {%4,%5,%6,%7}, {%8,%9}, {%0,%1,%2,%3};"
        : "+f"(c[0]), "+f"(c[1]), "+f"(c[2]), "+f"(c[3])
        : "r"(a[0]), "r"(a[1]), "r"(a[2]), "r"(a[3]), "r"(b0), "r"(b1));
}
__device__ __forceinline__ void cpa16(uint32_t d, const void* s) {
    asm volatile("cp.async.cg.shared.global [%0], [%1], 16;" :: "r"(d), "l"(s));
}
#define CP_COMMIT() asm volatile("cp.async.commit_group;" ::: "memory")
#define CP_WAIT0()  asm volatile("cp.async.wait_group 0;" ::: "memory")

__device__ __forceinline__ uint32_t pkh(float a, float b) {
    __half ha = __float2half(a), hb = __float2half(b);
    return (uint32_t)__half_as_ushort(ha) | ((uint32_t)__half_as_ushort(hb) << 16);
}

// ============ fused prep: policies + all weight/input conversions =============
__global__ void prep_all(const float* __restrict__ x,
                         const float* __restrict__ p1,
                         const float* __restrict__ p2,
                         const float* __restrict__ pf,
                         const float* __restrict__ W0,
                         const float* __restrict__ W1,
                         const float* __restrict__ W2,
                         const float* __restrict__ b2) {
    const int b = blockIdx.x;
    const int t = threadIdx.x;
    if (b == 0) {
        __shared__ float gs[8];
        if (t == 0) {
            float d = 0.f;
            for (int j = 0; j < 8; j++) d += pf[j];
            float inv = d > 0.f ? 1.f / d : 1.f;
            float acc = 1.f;
            for (int j = 7; j >= 0; --j) { acc *= inv; gs[j] = pf[j] * acc; }
        }
        __syncthreads();
        if (t < 8) {
            float r1 = 0.f;
            for (int f = 0; f < 8; f++) r1 += p1[t * 8 + f];
            float i1 = r1 > 0.f ? 1.f / r1 : 1.f;
            for (int f = 0; f < 8; f++)
                g_c1n[t * 8 + f] = p1[t * 8 + f] * i1;
        }
        if (t < 62) {
            float s = 0.f;
            for (int j = 0; j < 8; j++) s += gs[j] * b2[j * NC + t];
            g_gbias[t] = s;
        } else if (t < 64) {
            g_gbias[t] = 0.f;
        }
    } else if (b < 257) {
        int idx = (b - 1) * 256 + t;
        int n  = idx & 511;
        int r  = idx >> 9;          // (l*8+u)*8 + k8, < 128
        int k8 = r & 7;
        int ug = r >> 3;
        const float* W = (ug >= 8 ? W1 : W0) + ((size_t)(ug & 7) << 18);
        unsigned short hv[64];
        #pragma unroll 8
        for (int i = 0; i < 64; i++)
            hv[i] = __half_as_ushort(__float2half(W[(size_t)(k8 * 64 + i) * 512 + n]));
        __half* dst = g_wh + ((size_t)r * 512 + n) * 64;
        #pragma unroll
        for (int i = 0; i < 8; i++)
            *(uint4*)(dst + i * 8) = *(uint4*)(hv + i * 8);
    } else if (b < 1281) {
        __shared__ float c2s[64];
        if (t < 64) {
            int j = t >> 3;
            float d = 0.f;
            #pragma unroll
            for (int q = 0; q < 8; q++) d += pf[q];
            float inv = d > 0.f ? 1.f / d : 1.f;
            float gsj = pf[j];
            #pragma unroll
            for (int q = 0; q < 8; q++) if (q >= j) gsj *= inv;   // inv^(8-j)
            float r2 = 0.f;
            #pragma unroll
            for (int q = 0; q < 8; q++) r2 += p2[j * 8 + q];
            float i2 = r2 > 0.f ? 1.f / r2 : 1.f;
            c2s[t] = gsj * p2[t] * i2;
        }
        __syncthreads();
        int idx = (b - 257) * 256 + t;   // 262144 total
        int f = idx >> 15;
        int k512 = (idx >> 6) & 511;
        int n = idx & 63;
        float s = 0.f;
        if (n < NC) {
            #pragma unroll
            for (int j = 0; j < 8; j++)
                s = fmaf(c2s[j * 8 + f], W2[((size_t)(j * 512) + k512) * NC + n], s);
        }
        int k8 = k512 >> 6, kk = k512 & 63;
        g_w2h[((size_t)(f * 8 + k8) * 64 + n) * 64 + kk] = __float2half(s);
    } else {
        size_t off = ((size_t)(b - 1281) * 256 + t) << 2;
        float4 v = *(const float4*)(x + off);
        *(uint2*)(g_xh + off) = make_uint2(pkh(v.x, v.y), pkh(v.z, v.w));
    }
}

// ============= fp16 HMMA GEMM: C[u] = relu(A[u] @ W[u] + b[u]) ================
// M=16384, N=512, K=512. BM=128, BN=128, BK=64. 8 warps 4x2, warp tile 32x64.
// EXACT R12 configuration (measured best: 540.8us total, 205us/launch).
#define ROWB  144
#define PLANE (128 * ROWB)          // 18432
#define STG   (2 * PLANE)           // 36864
#define GEMM_SMEM (2 * STG)         // 73728

__global__ __launch_bounds__(256, 2)
void gemm_fp16(int srcSel, int layer, const float* __restrict__ bias, int outSel) {
    extern __shared__ __align__(16) char dsm[];
    __shared__ float sBias[512];
    const uint32_t sdyn = smem_to_u32(dsm);

    const int tid = threadIdx.x;
    const int wid = tid >> 5, lane = tid & 31;
    const int g = lane >> 2, t4 = lane & 3;
    const int wm = (wid >> 1) * 32;
    const int wn = (wid & 1) * 64;
    const int u  = blockIdx.z;
    const int bm = blockIdx.x * 128;
    const int bn = blockIdx.y * 128;

    // ldmatrix lane decodes (validated R5-R15)
    const int la  = (lane & 7) + ((lane >> 3) & 1) * 8;
    const int lk  = (lane >> 4) * 16;
    const int lbn = (lane & 7) + ((lane >> 4) & 1) * 8;
    const int lbk = ((lane >> 3) & 1) * 16;

    const __half* AU = (srcSel == 0) ? g_xh : (g_a1 + (size_t)u * SLAB);
    AU += (size_t)bm * HD;
    const __half* Wb = g_wh + (size_t)(layer * 8 + u) * 262144;
    __half* OH = (outSel ? g_h1 : g_h0) + (size_t)u * SLAB + (size_t)bm * HD + bn;

    ((float2*)sBias)[tid] = ((const float2*)(bias + u * HD))[tid];

    float acc[2][8][4];
    #pragma unroll
    for (int i = 0; i < 2; i++)
        #pragma unroll
        for (int j = 0; j < 8; j++)
            #pragma unroll
            for (int q = 0; q < 4; q++) acc[i][j][q] = 0.f;

    const int r0 = tid >> 3, q0 = tid & 7;   // staging lane map

    auto issue = [&](int kt, int bufI) {
        uint32_t sbuf = sdyn + bufI * STG;
        const __half* Ap = AU + kt * 64;
        const __half* Bp = Wb + (size_t)kt * 32768 + (size_t)bn * 64;
        #pragma unroll
        for (int i = 0; i < 4; i++) {
            int row = r0 + i * 32;
            cpa16(sbuf + row * ROWB + q0 * 16,         Ap + (size_t)row * HD + q0 * 8);
            cpa16(sbuf + PLANE + row * ROWB + q0 * 16, Bp + (size_t)row * 64 + q0 * 8);
        }
        CP_COMMIT();
    };

    issue(0, 0);

    #pragma unroll 1
    for (int kt = 0; kt < 8; ++kt) {
        const int s = kt & 1;
        CP_WAIT0();
        __syncthreads();
        if (kt < 7) issue(kt + 1, 1 - s);

        const uint32_t aB = sdyn + s * STG;
        const uint32_t bB = aB + PLANE;
        uint32_t af[2][2][4], bf[2][4][4];
        ldsm4(af[0][0], aB + (wm + la) * ROWB + lk);
        ldsm4(af[0][1], aB + (wm + 16 + la) * ROWB + lk);
        #pragma unroll
        for (int jp = 0; jp < 4; jp++)
            ldsm4(bf[0][jp], bB + (wn + 16 * jp + lbn) * ROWB + lbk);

        #pragma unroll
        for (int k16 = 0; k16 < 4; k16++) {
            const int cur = k16 & 1, nxt = cur ^ 1;
            if (k16 < 3) {
                const int kb = (k16 + 1) * 32;
                ldsm4(af[nxt][0], aB + (wm + la) * ROWB + kb + lk);
                ldsm4(af[nxt][1], aB + (wm + 16 + la) * ROWB + kb + lk);
                #pragma unroll
                for (int jp = 0; jp < 4; jp++)
                    ldsm4(bf[nxt][jp], bB + (wn + 16 * jp + lbn) * ROWB + kb + lbk);
            }
            #pragma unroll
            for (int jp = 0; jp < 4; jp++) {
                #pragma unroll
                for (int jj = 0; jj < 2; jj++) {
                    const int j = 2 * jp + jj;
                    mma16816(acc[0][j], af[cur][0], bf[cur][jp][2 * jj], bf[cur][jp][2 * jj + 1]);
                    mma16816(acc[1][j], af[cur][1], bf[cur][jp][2 * jj], bf[cur][jp][2 * jj + 1]);
                }
            }
        }
    }

    // ---- epilogue: bias + relu -> fp16 ----
    #pragma unroll
    for (int i = 0; i < 2; i++) {
        #pragma unroll
        for (int j = 0; j < 8; j++) {
            int cb = wn + 8 * j + t4 * 2;
            float b0 = sBias[bn + cb], b1 = sBias[bn + cb + 1];
            float v0 = acc[i][j][0] + b0, v1 = acc[i][j][1] + b1;
            float v2 = acc[i][j][2] + b0, v3 = acc[i][j][3] + b1;
            v0 = v0 > 0.f ? v0 : 0.f; v1 = v1 > 0.f ? v1 : 0.f;
            v2 = v2 > 0.f ? v2 : 0.f; v3 = v3 > 0.f ? v3 : 0.f;
            int m0 = wm + 16 * i + g;
            *(uint32_t*)(OH + (size_t)m0 * HD + cb)       = pkh(v0, v1);
            *(uint32_t*)(OH + (size_t)(m0 + 8) * HD + cb) = pkh(v2, v3);
        }
    }
}

// ---------------- aggregation: a1[t] = sum_f c1n[t,f]*h0[f] (fp16, 8/thread) ---
__global__ void agg1_kernel() {
    __shared__ float c1s[64];
    int t = threadIdx.x;
    if (t < 64) c1s[t] = g_c1n[t];
    __syncthreads();
    size_t off = ((size_t)blockIdx.x * 256 + t) << 3;   // 8 halves per thread
    float2 h[8][4];
    #pragma unroll
    for (int f = 0; f < 8; f++) {
        uint4 p = *(const uint4*)(g_h0 + (size_t)f * SLAB + off);
        h[f][0] = __half22float2(*(const __half2*)&p.x);
        h[f][1] = __half22float2(*(const __half2*)&p.y);
        h[f][2] = __half22float2(*(const __half2*)&p.z);
        h[f][3] = __half22float2(*(const __half2*)&p.w);
    }
    #pragma unroll
    for (int u = 0; u < 8; u++) {
        float s[8];
        #pragma unroll
        for (int q = 0; q < 8; q++) s[q] = 0.f;
        #pragma unroll
        for (int f = 0; f < 8; f++) {
            float c = c1s[u * 8 + f];
            #pragma unroll
            for (int q = 0; q < 4; q++) {
                s[2 * q]     = fmaf(c, h[f][q].x, s[2 * q]);
                s[2 * q + 1] = fmaf(c, h[f][q].y, s[2 * q + 1]);
            }
        }
        *(uint4*)(g_a1 + (size_t)u * SLAB + off) =
            make_uint4(pkh(s[0], s[1]), pkh(s[2], s[3]), pkh(s[4], s[5]), pkh(s[6], s[7]));
    }
}

// ============ fp16 output GEMM: out = sum_f h1[f] @ W2eff[f] + gbias ==========
// M=16384 (BM=64), N=64, K=4096. BK=128 (two k8 blocks/stage): 32 iters,
// 64 MMAs/warp/iter — amortizes per-iteration wait+sync overhead 2x.
#define OROWB  272                   // 128 halves + 16B pad (68 words ≡ 4 mod 32)
#define OPLANE (64 * OROWB)          // 17408
#define OSTG   (2 * OPLANE)          // 34816
#define OUT_SMEM (2 * OSTG)          // 69632

__global__ __launch_bounds__(256, 2)
void gemm_out_tc(float* __restrict__ Out) {
    extern __shared__ __align__(16) char dsm[];
    const uint32_t sdyn = smem_to_u32(dsm);
    const int tid = threadIdx.x;
    const int wid = tid >> 5, lane = tid & 31;
    const int g = lane >> 2, t4 = lane & 3;
    const int wm = (wid & 3) * 16;
    const int wn = (wid >> 2) * 32;
    const int bm = blockIdx.x * 64;

    const int la  = (lane & 7) + ((lane >> 3) & 1) * 8;
    const int lk  = (lane >> 4) * 16;
    const int lbn = (lane & 7) + ((lane >> 4) & 1) * 8;
    const int lbk = ((lane >> 3) & 1) * 16;

    float acc[4][4];
    #pragma unroll
    for (int j = 0; j < 4; j++)
        #pragma unroll
        for (int q = 0; q < 4; q++) acc[j][q] = 0.f;

    // staging: A tile 64 rows x 128 halves (1024 chunks), B same; 8 chunks/thread
    auto issue = [&](int it, int bufI) {
        uint32_t sbuf = sdyn + bufI * OSTG;
        int base = it * 2;                  // two k8 blocks per stage
        int f = base >> 3, k8 = base & 7;
        const __half* Ap  = g_h1 + (size_t)f * SLAB + (size_t)bm * HD + k8 * 64;
        const __half* Bp0 = g_w2h + (size_t)(f * 8 + k8) * 4096;
        #pragma unroll
        for (int i = 0; i < 4; i++) {
            int c = i * 256 + tid;
            int row = c >> 4, q = c & 15;
            cpa16(sbuf + row * OROWB + q * 16, Ap + (size_t)row * HD + q * 8);
        }
        #pragma unroll
        for (int i = 0; i < 4; i++) {
            int c = i * 256 + tid;
            int row = c >> 4, q = c & 15;
            const __half* src = (q < 8) ? (Bp0 + (size_t)row * 64 + q * 8)
                                        : (Bp0 + 4096 + (size_t)row * 64 + (q - 8) * 8);
            cpa16(sbuf + OPLANE + row * OROWB + q * 16, src);
        }
        CP_COMMIT();
    };

    issue(0, 0);

    #pragma unroll 1
    for (int it = 0; it < 32; ++it) {
        const int s = it & 1;
        CP_WAIT0();
        __syncthreads();
        if (it < 31) issue(it + 1, 1 - s);

        const uint32_t aB = sdyn + s * OSTG;
        const uint32_t bB = aB + OPLANE;
        uint32_t af[2][4], bf[2][2][4];
        ldsm4(af[0], aB + (wm + la) * OROWB + lk);
        #pragma unroll
        for (int jp = 0; jp < 2; jp++)
            ldsm4(bf[0][jp], bB + (wn + 16 * jp + lbn) * OROWB + lbk);

        #pragma unroll
        for (int k16 = 0; k16 < 8; k16++) {
            const int cur = k16 & 1, nxt = cur ^ 1;
            if (k16 < 7) {
                const int kb = (k16 + 1) * 32;
                ldsm4(af[nxt], aB + (wm + la) * OROWB + kb + lk);
                #pragma unroll
                for (int jp = 0; jp < 2; jp++)
                    ldsm4(bf[nxt][jp], bB + (wn + 16 * jp + lbn) * OROWB + kb + lbk);
            }
            #pragma unroll
            for (int jp = 0; jp < 2; jp++) {
                mma16816(acc[2 * jp],     af[cur], bf[cur][jp][0], bf[cur][jp][1]);
                mma16816(acc[2 * jp + 1], af[cur], bf[cur][jp][2], bf[cur][jp][3]);
            }
        }
    }

    // epilogue: + gbias, store (cols < NC)
    #pragma unroll
    for (int j = 0; j < 4; j++) {
        int c = wn + 8 * j + 2 * t4;
        float b0 = g_gbias[c], b1 = g_gbias[c + 1];
        int m0 = bm + wm + g;
        float v0 = acc[j][0] + b0, v1 = acc[j][1] + b1;
        float v2 = acc[j][2] + b0, v3 = acc[j][3] + b1;
        if (c < NC)     Out[(size_t)m0 * NC + c]           = v0;
        if (c + 1 < NC) Out[(size_t)m0 * NC + c + 1]       = v1;
        if (c < NC)     Out[(size_t)(m0 + 8) * NC + c]     = v2;
        if (c + 1 < NC) Out[(size_t)(m0 + 8) * NC + c + 1] = v3;
    }
}

// ---------------- launch ------------------------------------------------------
extern "C" void kernel_launch(void* const* d_in, const int* in_sizes, int n_in,
                              void* d_out, int out_size) {
    const float* x  = (const float*)d_in[0];
    const float* p1 = (const float*)d_in[1];
    const float* p2 = (const float*)d_in[2];
    const float* pf = (const float*)d_in[3];
    const float* W0 = (const float*)d_in[4];
    const float* b0 = (const float*)d_in[5];
    const float* W1 = (const float*)d_in[6];
    const float* b1 = (const float*)d_in[7];
    const float* W2 = (const float*)d_in[8];
    const float* b2 = (const float*)d_in[9];
    float* out = (float*)d_out;

    cudaFuncSetAttribute(gemm_fp16, cudaFuncAttributeMaxDynamicSharedMemorySize, GEMM_SMEM);
    cudaFuncSetAttribute(gemm_out_tc, cudaFuncAttributeMaxDynamicSharedMemorySize, OUT_SMEM);

    // all policy folds + fp16 conversions in one launch
    prep_all<<<9473, 256>>>(x, p1, p2, pf, W0, W1, W2, b2);

    // stage A: h0[u] = relu(x @ W0[u] + b0[u]) -> g_h0 fp16
    gemm_fp16<<<dim3(128, 4, 8), 256, GEMM_SMEM>>>(0, 0, b0, 0);

    // aggregation: a1 = c1n-mix(h0) -> g_a1 fp16
    agg1_kernel<<<4096, 256>>>();

    // stage C: h1[u] = relu(a1[u] @ W1[u] + b1[u]) -> g_h1 fp16
    gemm_fp16<<<dim3(128, 4, 8), 256, GEMM_SMEM>>>(1, 1, b1, 1);

    // output: out = sum_f h1[f] @ W2eff[f] + gbias
    gemm_out_tc<<<256, 256, OUT_SMEM>>>(out);
}

// round 17
// speedup vs baseline: 1.7232x; 1.0049x over previous
#include <cuda_runtime.h>
#include <cuda_fp16.h>
#include <cstdint>

// Problem constants
#define BSZ 16384
#define HD  512
#define NC  62
#define UU  8
#define SLAB  ((size_t)BSZ * HD)   // per-unit plane elems (8M)

// ---------------- scratch (device globals; no allocation allowed) -------------
__device__ __align__(16) __half g_xh[(size_t)BSZ * HD];            // x fp16
__device__ __align__(16) __half g_h0[(size_t)UU * BSZ * HD];       // h0 fp16
__device__ __align__(16) __half g_a1[(size_t)UU * BSZ * HD];       // a1 fp16
__device__ __align__(16) __half g_h1[(size_t)UU * BSZ * HD];       // h1 fp16
__device__ __align__(16) __half g_wh[(size_t)2 * 8 * 8 * 512 * 64];  // [(l*8+u)][k8][n512][k64]
__device__ __align__(16) __half g_w2h[(size_t)8 * 8 * 64 * 64];      // [(f*8+k8)][n64][k64]
__device__ float g_c1n[64];
__device__ float g_gbias[64];

// ---------------- helpers -----------------------------------------------------
__device__ __forceinline__ uint32_t smem_to_u32(const void* p) {
    uint32_t a;
    asm("{ .reg .u64 t; cvta.to.shared.u64 t, %1; cvt.u32.u64 %0, t; }" : "=r"(a) : "l"(p));
    return a;
}
__device__ __forceinline__ void ldsm4(uint32_t* r, uint32_t addr) {
    asm volatile("ldmatrix.sync.aligned.m8n8.x4.shared.b16 {%0,%1,%2,%3}, [%4];"
        : "=r"(r[0]), "=r"(r[1]), "=r"(r[2]), "=r"(r[3]) : "r"(addr));
}
__device__ __forceinline__ void mma16816(float* c, const uint32_t* a,
                                         uint32_t b0, uint32_t b1) {
    asm volatile(
        "mma.sync.aligned.m16n8k16.row.col.f32.f16.f16.f32 "
        "{%0,%1,%2,%3}, {%4,%5,%6,%7}, {%8,%9}, {%0,%1,%2,%3};"
        : "+f"(c[0]), "+f"(c[1]), "+f"(c[2]), "+f"(c[3])
        : "r"(a[0]), "r"(a[1]), "r"(a[2]), "r"(a[3]), "r"(b0), "r"(b1));
}
__device__ __forceinline__ void cpa16(uint32_t d, const void* s) {
    asm volatile("cp.async.cg.shared.global [%0], [%1], 16;" :: "r"(d), "l"(s));
}
#define CP_COMMIT() asm volatile("cp.async.commit_group;" ::: "memory")
#define CP_WAIT0()  asm volatile("cp.async.wait_group 0;" ::: "memory")

__device__ __forceinline__ uint32_t pkh(float a, float b) {
    __half ha = __float2half(a), hb = __float2half(b);
    return (uint32_t)__half_as_ushort(ha) | ((uint32_t)__half_as_ushort(hb) << 16);
}

// ============ fused prep: policies + all weight/input conversions =============
__global__ void prep_all(const float* __restrict__ x,
                         const float* __restrict__ p1,
                         const float* __restrict__ p2,
                         const float* __restrict__ pf,
                         const float* __restrict__ W0,
                         const float* __restrict__ W1,
                         const float* __restrict__ W2,
                         const float* __restrict__ b2) {
    const int b = blockIdx.x;
    const int t = threadIdx.x;
    if (b == 0) {
        __shared__ float gs[8];
        if (t == 0) {
            float d = 0.f;
            for (int j = 0; j < 8; j++) d += pf[j];
            float inv = d > 0.f ? 1.f / d : 1.f;
            float acc = 1.f;
            for (int j = 7; j >= 0; --j) { acc *= inv; gs[j] = pf[j] * acc; }
        }
        __syncthreads();
        if (t < 8) {
            float r1 = 0.f;
            for (int f = 0; f < 8; f++) r1 += p1[t * 8 + f];
            float i1 = r1 > 0.f ? 1.f / r1 : 1.f;
            for (int f = 0; f < 8; f++)
                g_c1n[t * 8 + f] = p1[t * 8 + f] * i1;
        }
        if (t < 62) {
            float s = 0.f;
            for (int j = 0; j < 8; j++) s += gs[j] * b2[j * NC + t];
            g_gbias[t] = s;
        } else if (t < 64) {
            g_gbias[t] = 0.f;
        }
    } else if (b < 257) {
        int idx = (b - 1) * 256 + t;
        int n  = idx & 511;
        int r  = idx >> 9;          // (l*8+u)*8 + k8, < 128
        int k8 = r & 7;
        int ug = r >> 3;
        const float* W = (ug >= 8 ? W1 : W0) + ((size_t)(ug & 7) << 18);
        unsigned short hv[64];
        #pragma unroll 8
        for (int i = 0; i < 64; i++)
            hv[i] = __half_as_ushort(__float2half(W[(size_t)(k8 * 64 + i) * 512 + n]));
        __half* dst = g_wh + ((size_t)r * 512 + n) * 64;
        #pragma unroll
        for (int i = 0; i < 8; i++)
            *(uint4*)(dst + i * 8) = *(uint4*)(hv + i * 8);
    } else if (b < 1281) {
        __shared__ float c2s[64];
        if (t < 64) {
            int j = t >> 3;
            float d = 0.f;
            #pragma unroll
            for (int q = 0; q < 8; q++) d += pf[q];
            float inv = d > 0.f ? 1.f / d : 1.f;
            float gsj = pf[j];
            #pragma unroll
            for (int q = 0; q < 8; q++) if (q >= j) gsj *= inv;   // inv^(8-j)
            float r2 = 0.f;
            #pragma unroll
            for (int q = 0; q < 8; q++) r2 += p2[j * 8 + q];
            float i2 = r2 > 0.f ? 1.f / r2 : 1.f;
            c2s[t] = gsj * p2[t] * i2;
        }
        __syncthreads();
        int idx = (b - 257) * 256 + t;   // 262144 total
        int f = idx >> 15;
        int k512 = (idx >> 6) & 511;
        int n = idx & 63;
        float s = 0.f;
        if (n < NC) {
            #pragma unroll
            for (int j = 0; j < 8; j++)
                s = fmaf(c2s[j * 8 + f], W2[((size_t)(j * 512) + k512) * NC + n], s);
        }
        int k8 = k512 >> 6, kk = k512 & 63;
        g_w2h[((size_t)(f * 8 + k8) * 64 + n) * 64 + kk] = __float2half(s);
    } else {
        size_t off = ((size_t)(b - 1281) * 256 + t) << 2;
        float4 v = *(const float4*)(x + off);
        *(uint2*)(g_xh + off) = make_uint2(pkh(v.x, v.y), pkh(v.z, v.w));
    }
}

// ============= fp16 HMMA GEMM: C[u] = relu(A[u] @ W[u] + b[u]) ================
// M=16384, N=512, K=512. BM=64, BN=128, BK=64. 128 thr (4 warps 2m x 2n),
// warp tile 32x64 (unchanged). 4 CTAs/SM -> 4 desynced barrier domains.
#define ROWB  144
#define APLANE (64 * ROWB)           // 9216
#define BPLANE (128 * ROWB)          // 18432
#define STG    (APLANE + BPLANE)     // 27648
#define GEMM_SMEM (2 * STG)          // 55296

__global__ __launch_bounds__(128, 4)
void gemm_fp16(int srcSel, int layer, const float* __restrict__ bias, int outSel) {
    extern __shared__ __align__(16) char dsm[];
    __shared__ float sBias[512];
    const uint32_t sdyn = smem_to_u32(dsm);

    const int tid = threadIdx.x;
    const int wid = tid >> 5, lane = tid & 31;
    const int g = lane >> 2, t4 = lane & 3;
    const int wm = (wid >> 1) * 32;       // 2 warp rows over BM=64
    const int wn = (wid & 1) * 64;        // 2 warp cols over BN=128
    const int u  = blockIdx.z;
    const int bm = blockIdx.x * 64;
    const int bn = blockIdx.y * 128;

    // ldmatrix lane decodes (validated R5-R16)
    const int la  = (lane & 7) + ((lane >> 3) & 1) * 8;
    const int lk  = (lane >> 4) * 16;
    const int lbn = (lane & 7) + ((lane >> 4) & 1) * 8;
    const int lbk = ((lane >> 3) & 1) * 16;

    const __half* AU = (srcSel == 0) ? g_xh : (g_a1 + (size_t)u * SLAB);
    AU += (size_t)bm * HD;
    const __half* Wb = g_wh + (size_t)(layer * 8 + u) * 262144;
    __half* OH = (outSel ? g_h1 : g_h0) + (size_t)u * SLAB + (size_t)bm * HD + bn;

    ((float4*)sBias)[tid] = ((const float4*)(bias + u * HD))[tid];

    float acc[2][8][4];
    #pragma unroll
    for (int i = 0; i < 2; i++)
        #pragma unroll
        for (int j = 0; j < 8; j++)
            #pragma unroll
            for (int q = 0; q < 4; q++) acc[i][j][q] = 0.f;

    const int r0 = tid >> 3, q0 = tid & 7;   // staging lane map (16 rows/step)

    auto issue = [&](int kt, int bufI) {
        uint32_t sbuf = sdyn + bufI * STG;
        const __half* Ap = AU + kt * 64;
        const __half* Bp = Wb + (size_t)kt * 32768 + (size_t)bn * 64;
        #pragma unroll
        for (int i = 0; i < 4; i++) {       // A: 64 rows
            int row = r0 + i * 16;
            cpa16(sbuf + row * ROWB + q0 * 16, Ap + (size_t)row * HD + q0 * 8);
        }
        #pragma unroll
        for (int i = 0; i < 8; i++) {       // B: 128 rows
            int row = r0 + i * 16;
            cpa16(sbuf + APLANE + row * ROWB + q0 * 16, Bp + (size_t)row * 64 + q0 * 8);
        }
        CP_COMMIT();
    };

    issue(0, 0);

    #pragma unroll 1
    for (int kt = 0; kt < 8; ++kt) {
        const int s = kt & 1;
        CP_WAIT0();
        __syncthreads();
        if (kt < 7) issue(kt + 1, 1 - s);

        const uint32_t aB = sdyn + s * STG;
        const uint32_t bB = aB + APLANE;
        uint32_t af[2][2][4], bf[2][4][4];
        ldsm4(af[0][0], aB + (wm + la) * ROWB + lk);
        ldsm4(af[0][1], aB + (wm + 16 + la) * ROWB + lk);
        #pragma unroll
        for (int jp = 0; jp < 4; jp++)
            ldsm4(bf[0][jp], bB + (wn + 16 * jp + lbn) * ROWB + lbk);

        #pragma unroll
        for (int k16 = 0; k16 < 4; k16++) {
            const int cur = k16 & 1, nxt = cur ^ 1;
            if (k16 < 3) {
                const int kb = (k16 + 1) * 32;
                ldsm4(af[nxt][0], aB + (wm + la) * ROWB + kb + lk);
                ldsm4(af[nxt][1], aB + (wm + 16 + la) * ROWB + kb + lk);
                #pragma unroll
                for (int jp = 0; jp < 4; jp++)
                    ldsm4(bf[nxt][jp], bB + (wn + 16 * jp + lbn) * ROWB + kb + lbk);
            }
            #pragma unroll
            for (int jp = 0; jp < 4; jp++) {
                #pragma unroll
                for (int jj = 0; jj < 2; jj++) {
                    const int j = 2 * jp + jj;
                    mma16816(acc[0][j], af[cur][0], bf[cur][jp][2 * jj], bf[cur][jp][2 * jj + 1]);
                    mma16816(acc[1][j], af[cur][1], bf[cur][jp][2 * jj], bf[cur][jp][2 * jj + 1]);
                }
            }
        }
    }

    // ---- epilogue: bias + relu -> fp16 ----
    #pragma unroll
    for (int i = 0; i < 2; i++) {
        #pragma unroll
        for (int j = 0; j < 8; j++) {
            int cb = wn + 8 * j + t4 * 2;
            float b0 = sBias[bn + cb], b1 = sBias[bn + cb + 1];
            float v0 = acc[i][j][0] + b0, v1 = acc[i][j][1] + b1;
            float v2 = acc[i][j][2] + b0, v3 = acc[i][j][3] + b1;
            v0 = v0 > 0.f ? v0 : 0.f; v1 = v1 > 0.f ? v1 : 0.f;
            v2 = v2 > 0.f ? v2 : 0.f; v3 = v3 > 0.f ? v3 : 0.f;
            int m0 = wm + 16 * i + g;
            *(uint32_t*)(OH + (size_t)m0 * HD + cb)       = pkh(v0, v1);
            *(uint32_t*)(OH + (size_t)(m0 + 8) * HD + cb) = pkh(v2, v3);
        }
    }
}

// ---------------- aggregation: a1[t] = sum_f c1n[t,f]*h0[f] (fp16, 8/thread) ---
__global__ void agg1_kernel() {
    __shared__ float c1s[64];
    int t = threadIdx.x;
    if (t < 64) c1s[t] = g_c1n[t];
    __syncthreads();
    size_t off = ((size_t)blockIdx.x * 256 + t) << 3;   // 8 halves per thread
    float2 h[8][4];
    #pragma unroll
    for (int f = 0; f < 8; f++) {
        uint4 p = *(const uint4*)(g_h0 + (size_t)f * SLAB + off);
        h[f][0] = __half22float2(*(const __half2*)&p.x);
        h[f][1] = __half22float2(*(const __half2*)&p.y);
        h[f][2] = __half22float2(*(const __half2*)&p.z);
        h[f][3] = __half22float2(*(const __half2*)&p.w);
    }
    #pragma unroll
    for (int u = 0; u < 8; u++) {
        float s[8];
        #pragma unroll
        for (int q = 0; q < 8; q++) s[q] = 0.f;
        #pragma unroll
        for (int f = 0; f < 8; f++) {
            float c = c1s[u * 8 + f];
            #pragma unroll
            for (int q = 0; q < 4; q++) {
                s[2 * q]     = fmaf(c, h[f][q].x, s[2 * q]);
                s[2 * q + 1] = fmaf(c, h[f][q].y, s[2 * q + 1]);
            }
        }
        *(uint4*)(g_a1 + (size_t)u * SLAB + off) =
            make_uint4(pkh(s[0], s[1]), pkh(s[2], s[3]), pkh(s[4], s[5]), pkh(s[6], s[7]));
    }
}

// ============ fp16 output GEMM: out = sum_f h1[f] @ W2eff[f] + gbias ==========
// M=16384 (BM=64), N=64, K=4096. BK=128 (two k8 blocks/stage): 32 iters.
#define OROWB  272                   // 128 halves + 16B pad (68 words ≡ 4 mod 32)
#define OPLANE (64 * OROWB)          // 17408
#define OSTG   (2 * OPLANE)          // 34816
#define OUT_SMEM (2 * OSTG)          // 69632

__global__ __launch_bounds__(256, 2)
void gemm_out_tc(float* __restrict__ Out) {
    extern __shared__ __align__(16) char dsm[];
    const uint32_t sdyn = smem_to_u32(dsm);
    const int tid = threadIdx.x;
    const int wid = tid >> 5, lane = tid & 31;
    const int g = lane >> 2, t4 = lane & 3;
    const int wm = (wid & 3) * 16;
    const int wn = (wid >> 2) * 32;
    const int bm = blockIdx.x * 64;

    const int la  = (lane & 7) + ((lane >> 3) & 1) * 8;
    const int lk  = (lane >> 4) * 16;
    const int lbn = (lane & 7) + ((lane >> 4) & 1) * 8;
    const int lbk = ((lane >> 3) & 1) * 16;

    float acc[4][4];
    #pragma unroll
    for (int j = 0; j < 4; j++)
        #pragma unroll
        for (int q = 0; q < 4; q++) acc[j][q] = 0.f;

    auto issue = [&](int it, int bufI) {
        uint32_t sbuf = sdyn + bufI * OSTG;
        int base = it * 2;
        int f = base >> 3, k8 = base & 7;
        const __half* Ap  = g_h1 + (size_t)f * SLAB + (size_t)bm * HD + k8 * 64;
        const __half* Bp0 = g_w2h + (size_t)(f * 8 + k8) * 4096;
        #pragma unroll
        for (int i = 0; i < 4; i++) {
            int c = i * 256 + tid;
            int row = c >> 4, q = c & 15;
            cpa16(sbuf + row * OROWB + q * 16, Ap + (size_t)row * HD + q * 8);
        }
        #pragma unroll
        for (int i = 0; i < 4; i++) {
            int c = i * 256 + tid;
            int row = c >> 4, q = c & 15;
            const __half* src = (q < 8) ? (Bp0 + (size_t)row * 64 + q * 8)
                                        : (Bp0 + 4096 + (size_t)row * 64 + (q - 8) * 8);
            cpa16(sbuf + OPLANE + row * OROWB + q * 16, src);
        }
        CP_COMMIT();
    };

    issue(0, 0);

    #pragma unroll 1
    for (int it = 0; it < 32; ++it) {
        const int s = it & 1;
        CP_WAIT0();
        __syncthreads();
        if (it < 31) issue(it + 1, 1 - s);

        const uint32_t aB = sdyn + s * OSTG;
        const uint32_t bB = aB + OPLANE;
        uint32_t af[2][4], bf[2][2][4];
        ldsm4(af[0], aB + (wm + la) * OROWB + lk);
        #pragma unroll
        for (int jp = 0; jp < 2; jp++)
            ldsm4(bf[0][jp], bB + (wn + 16 * jp + lbn) * OROWB + lbk);

        #pragma unroll
        for (int k16 = 0; k16 < 8; k16++) {
            const int cur = k16 & 1, nxt = cur ^ 1;
            if (k16 < 7) {
                const int kb = (k16 + 1) * 32;
                ldsm4(af[nxt], aB + (wm + la) * OROWB + kb + lk);
                #pragma unroll
                for (int jp = 0; jp < 2; jp++)
                    ldsm4(bf[nxt][jp], bB + (wn + 16 * jp + lbn) * OROWB + kb + lbk);
            }
            #pragma unroll
            for (int jp = 0; jp < 2; jp++) {
                mma16816(acc[2 * jp],     af[cur], bf[cur][jp][0], bf[cur][jp][1]);
                mma16816(acc[2 * jp + 1], af[cur], bf[cur][jp][2], bf[cur][jp][3]);
            }
        }
    }

    // epilogue: + gbias, store (cols < NC)
    #pragma unroll
    for (int j = 0; j < 4; j++) {
        int c = wn + 8 * j + 2 * t4;
        float b0 = g_gbias[c], b1 = g_gbias[c + 1];
        int m0 = bm + wm + g;
        float v0 = acc[j][0] + b0, v1 = acc[j][1] + b1;
        float v2 = acc[j][2] + b0, v3 = acc[j][3] + b1;
        if (c < NC)     Out[(size_t)m0 * NC + c]           = v0;
        if (c + 1 < NC) Out[(size_t)m0 * NC + c + 1]       = v1;
        if (c < NC)     Out[(size_t)(m0 + 8) * NC + c]     = v2;
        if (c + 1 < NC) Out[(size_t)(m0 + 8) * NC + c + 1] = v3;
    }
}

// ---------------- launch ------------------------------------------------------
extern "C" void kernel_launch(void* const* d_in, const int* in_sizes, int n_in,
                              void* d_out, int out_size) {
    const float* x  = (const float*)d_in[0];
    const float* p1 = (const float*)d_in[1];
    const float* p2 = (const float*)d_in[2];
    const float* pf = (const float*)d_in[3];
    const float* W0 = (const float*)d_in[4];
    const float* b0 = (const float*)d_in[5];
    const float* W1 = (const float*)d_in[6];
    const float* b1 = (const float*)d_in[7];
    const float* W2 = (const float*)d_in[8];
    const float* b2 = (const float*)d_in[9];
    float* out = (float*)d_out;

    cudaFuncSetAttribute(gemm_fp16, cudaFuncAttributeMaxDynamicSharedMemorySize, GEMM_SMEM);
    cudaFuncSetAttribute(gemm_out_tc, cudaFuncAttributeMaxDynamicSharedMemorySize, OUT_SMEM);

    // all policy folds + fp16 conversions in one launch
    prep_all<<<9473, 256>>>(x, p1, p2, pf, W0, W1, W2, b2);

    // stage A: h0[u] = relu(x @ W0[u] + b0[u]) -> g_h0 fp16
    gemm_fp16<<<dim3(256, 4, 8), 128, GEMM_SMEM>>>(0, 0, b0, 0);

    // aggregation: a1 = c1n-mix(h0) -> g_a1 fp16
    agg1_kernel<<<4096, 256>>>();

    // stage C: h1[u] = relu(a1[u] @ W1[u] + b1[u]) -> g_h1 fp16
    gemm_fp16<<<dim3(256, 4, 8), 128, GEMM_SMEM>>>(1, 1, b1, 1);

    // output: out = sum_f h1[f] @ W2eff[f] + gbias
    gemm_out_tc<<<256, 256, OUT_SMEM>>>(out);
}